// round 1
// baseline (speedup 1.0000x reference)
#include <cuda_runtime.h>
#include <cstdint>

#define N_PRE   1024
#define N_POST  2048
#define SEQ_T   4096
#define DECAY   0.9f
#define V_TH    1.0f
#define MAXA    192            // max active pre-synapses per timestep (mean 102, sd 9.6; 192 ~ 9 sigma)

// ---------------- device scratch (static allocation only; no cudaMalloc allowed) ---------
__device__ float g_WT[N_PRE * (size_t)N_POST];          // W transposed: [p][n], 8 MB (L2-resident)
__device__ int   g_cnt[SEQ_T];                          // active count per timestep
__device__ int   g_idx[SEQ_T * MAXA];                   // active pre indices per timestep
__device__ float g_cur[(size_t)SEQ_T * N_POST];         // currents in [t][n] layout, 32 MB

// ---------------- kernel 1: transpose W [n][p] -> WT [p][n] ------------------------------
__global__ void k_transpose(const float* __restrict__ W) {
    __shared__ float tile[32][33];
    const int p0 = blockIdx.x * 32;
    const int n0 = blockIdx.y * 32;
    const int tx = threadIdx.x, ty = threadIdx.y;   // block (32, 8)
#pragma unroll
    for (int i = 0; i < 32; i += 8)
        tile[ty + i][tx] = W[(size_t)(n0 + ty + i) * N_PRE + p0 + tx];
    __syncthreads();
#pragma unroll
    for (int i = 0; i < 32; i += 8)
        g_WT[(size_t)(p0 + ty + i) * N_POST + n0 + tx] = tile[tx][ty + i];
}

// ---------------- kernel 2: build per-timestep active index lists ------------------------
__global__ void k_build_lists(const float* __restrict__ stim) {
    const int t = blockIdx.x * blockDim.x + threadIdx.x;
    if (t >= SEQ_T) return;
    int cnt = 0;
    int* lp = &g_idx[t * MAXA];
    for (int p = 0; p < N_PRE; p++) {
        // coalesced across threads (consecutive t, fixed p)
        if (stim[(size_t)p * SEQ_T + t] > 0.5f) {
            if (cnt < MAXA) lp[cnt] = p;
            cnt++;
        }
    }
    g_cnt[t] = cnt < MAXA ? cnt : MAXA;
}

// ---------------- kernel 3: sparse gather-accumulate: cur[t][n] = sum_{active p} WT[p][n]
// grid (SEQ_T, 2), block 256. Each thread owns one float4 of n (4 neurons).
__global__ void __launch_bounds__(256) k_gather() {
    const int t  = blockIdx.x;
    const int n4 = blockIdx.y * 256 + threadIdx.x;          // float4 index into 2048 n (0..511)
    const int c  = g_cnt[t];
    const int* __restrict__ lp = &g_idx[t * MAXA];

    float4 a0 = make_float4(0.f, 0.f, 0.f, 0.f);
    float4 a1 = make_float4(0.f, 0.f, 0.f, 0.f);
    float4 a2 = make_float4(0.f, 0.f, 0.f, 0.f);
    float4 a3 = make_float4(0.f, 0.f, 0.f, 0.f);

    int j = 0;
    for (; j + 4 <= c; j += 4) {
        const int p0 = lp[j], p1 = lp[j + 1], p2 = lp[j + 2], p3 = lp[j + 3];
        float4 w0 = ((const float4*)(g_WT + (size_t)p0 * N_POST))[n4];
        float4 w1 = ((const float4*)(g_WT + (size_t)p1 * N_POST))[n4];
        float4 w2 = ((const float4*)(g_WT + (size_t)p2 * N_POST))[n4];
        float4 w3 = ((const float4*)(g_WT + (size_t)p3 * N_POST))[n4];
        a0.x += w0.x; a0.y += w0.y; a0.z += w0.z; a0.w += w0.w;
        a1.x += w1.x; a1.y += w1.y; a1.z += w1.z; a1.w += w1.w;
        a2.x += w2.x; a2.y += w2.y; a2.z += w2.z; a2.w += w2.w;
        a3.x += w3.x; a3.y += w3.y; a3.z += w3.z; a3.w += w3.w;
    }
    for (; j < c; j++) {
        const int p0 = lp[j];
        float4 w0 = ((const float4*)(g_WT + (size_t)p0 * N_POST))[n4];
        a0.x += w0.x; a0.y += w0.y; a0.z += w0.z; a0.w += w0.w;
    }
    // combine partials (keeps deterministic order per lane; close to ascending-p fp32 sum)
    float4 s;
    s.x = (a0.x + a1.x) + (a2.x + a3.x);
    s.y = (a0.y + a1.y) + (a2.y + a3.y);
    s.z = (a0.z + a1.z) + (a2.z + a3.z);
    s.w = (a0.w + a1.w) + (a2.w + a3.w);
    ((float4*)(g_cur + (size_t)t * N_POST))[n4] = s;
}

// ---------------- kernel 4: LIF scan over t, transposed coalesced output -----------------
// grid 32 blocks x 32 threads; each thread owns 2 neuron chains (ILP to hide FFMA/FSEL latency)
#define TT 32
__global__ void __launch_bounds__(32) k_lif_scan(float* __restrict__ out) {
    __shared__ float sh_s[64][TT + 1];
    __shared__ float sh_v[64][TT + 1];
    const int tid = threadIdx.x;              // 0..31
    const int nb  = blockIdx.x * 64;          // 64 neurons per block
    const int n0  = nb + tid;
    const int n1  = nb + 32 + tid;

    float* __restrict__ out_s = out;
    float* __restrict__ out_v = out + (size_t)N_POST * SEQ_T;

    float v0 = 0.f, v1 = 0.f;

    for (int t0 = 0; t0 < SEQ_T; t0 += TT) {
        float c0[TT], c1[TT];
        // batched, independent, coalesced loads (deep MLP)
#pragma unroll
        for (int k = 0; k < TT; k++) {
            c0[k] = g_cur[(size_t)(t0 + k) * N_POST + n0];
            c1[k] = g_cur[(size_t)(t0 + k) * N_POST + n1];
        }
        // two interleaved dependency chains
#pragma unroll
        for (int k = 0; k < TT; k++) {
            v0 = v0 * DECAY + c0[k];
            float s0 = (v0 >= V_TH) ? 1.f : 0.f;
            v0 = (v0 >= V_TH) ? 0.f : v0;
            sh_s[tid][k] = s0;
            sh_v[tid][k] = v0;

            v1 = v1 * DECAY + c1[k];
            float s1 = (v1 >= V_TH) ? 1.f : 0.f;
            v1 = (v1 >= V_TH) ? 0.f : v1;
            sh_s[32 + tid][k] = s1;
            sh_v[32 + tid][k] = v1;
        }
        __syncthreads();
        // transposed write-out: each warp iteration writes one full row of 32 t (128B, coalesced)
#pragma unroll 4
        for (int i = tid; i < 64 * TT; i += 32) {
            const int r  = i >> 5;      // neuron row within block
            const int cq = i & 31;      // timestep within tile
            out_s[(size_t)(nb + r) * SEQ_T + t0 + cq] = sh_s[r][cq];
            out_v[(size_t)(nb + r) * SEQ_T + t0 + cq] = sh_v[r][cq];
        }
        __syncthreads();
    }
}

// ---------------- launch --------------------------------------------------------------
extern "C" void kernel_launch(void* const* d_in, const int* in_sizes, int n_in,
                              void* d_out, int out_size) {
    const float* stim = (const float*)d_in[0];   // [N_PRE, SEQ_T]
    const float* W    = (const float*)d_in[1];   // [N_POST, N_PRE]
    // defensive: auto-detect input order by element counts (they differ: 4M vs 2M)
    if (n_in >= 2 && in_sizes[0] == N_POST * N_PRE && in_sizes[1] == N_PRE * SEQ_T) {
        const float* tmp = stim; stim = W; W = tmp;
    }
    float* out = (float*)d_out;

    // 1) transpose W  and 2) build active lists (independent; same stream serializes anyway)
    k_transpose<<<dim3(N_PRE / 32, N_POST / 32), dim3(32, 8)>>>(W);
    k_build_lists<<<SEQ_T / 256, 256>>>(stim);

    // 3) sparse gather: currents[t][n]
    k_gather<<<dim3(SEQ_T, N_POST / 1024), 256>>>();

    // 4) LIF scan + transposed output
    k_lif_scan<<<N_POST / 64, 32>>>(out);
}

// round 2
// speedup vs baseline: 1.1359x; 1.1359x over previous
#include <cuda_runtime.h>
#include <cstdint>

#define N_PRE   1024
#define N_POST  2048
#define SEQ_T   4096
#define DECAY   0.9f
#define V_TH    1.0f
#define MAXA    192            // max active pre-synapses per timestep (mean 102, sd 9.6; 192 ~ 9 sigma)

// ---------------- device scratch (static allocation only; no cudaMalloc allowed) ---------
__device__ float g_WT[N_PRE * (size_t)N_POST];          // W transposed: [p][n], 8 MB (L2-resident)
__device__ int   g_cnt[SEQ_T];                          // active count per timestep
__device__ int   g_idx[SEQ_T * MAXA];                   // active pre indices per timestep
__device__ float g_cur[(size_t)SEQ_T * N_POST];         // currents in [t][n] layout, 32 MB

// ---------------- kernel 1: transpose W [n][p] -> WT [p][n] ------------------------------
__global__ void k_transpose(const float* __restrict__ W) {
    __shared__ float tile[32][33];
    const int p0 = blockIdx.x * 32;
    const int n0 = blockIdx.y * 32;
    const int tx = threadIdx.x, ty = threadIdx.y;   // block (32, 8)
#pragma unroll
    for (int i = 0; i < 32; i += 8)
        tile[ty + i][tx] = W[(size_t)(n0 + ty + i) * N_PRE + p0 + tx];
    __syncthreads();
#pragma unroll
    for (int i = 0; i < 32; i += 8)
        g_WT[(size_t)(p0 + ty + i) * N_POST + n0 + tx] = tile[tx][ty + i];
}

// ---------------- kernel 2: build per-timestep active index lists ------------------------
__global__ void k_build_lists(const float* __restrict__ stim) {
    const int t = blockIdx.x * blockDim.x + threadIdx.x;
    if (t >= SEQ_T) return;
    int cnt = 0;
    int* lp = &g_idx[t * MAXA];
    for (int p = 0; p < N_PRE; p++) {
        // coalesced across threads (consecutive t, fixed p)
        if (stim[(size_t)p * SEQ_T + t] > 0.5f) {
            if (cnt < MAXA) lp[cnt] = p;
            cnt++;
        }
    }
    g_cnt[t] = cnt < MAXA ? cnt : MAXA;
}

// ---------------- kernel 3: sparse gather-accumulate: cur[t][n] = sum_{active p} WT[p][n]
// grid (SEQ_T, 2), block 256. Each thread owns one float4 of n (4 neurons).
__global__ void __launch_bounds__(256) k_gather() {
    const int t  = blockIdx.x;
    const int n4 = blockIdx.y * 256 + threadIdx.x;          // float4 index into 2048 n (0..511)
    const int c  = g_cnt[t];
    const int* __restrict__ lp = &g_idx[t * MAXA];

    float4 a0 = make_float4(0.f, 0.f, 0.f, 0.f);
    float4 a1 = make_float4(0.f, 0.f, 0.f, 0.f);
    float4 a2 = make_float4(0.f, 0.f, 0.f, 0.f);
    float4 a3 = make_float4(0.f, 0.f, 0.f, 0.f);

    int j = 0;
    for (; j + 4 <= c; j += 4) {
        const int p0 = lp[j], p1 = lp[j + 1], p2 = lp[j + 2], p3 = lp[j + 3];
        float4 w0 = ((const float4*)(g_WT + (size_t)p0 * N_POST))[n4];
        float4 w1 = ((const float4*)(g_WT + (size_t)p1 * N_POST))[n4];
        float4 w2 = ((const float4*)(g_WT + (size_t)p2 * N_POST))[n4];
        float4 w3 = ((const float4*)(g_WT + (size_t)p3 * N_POST))[n4];
        a0.x += w0.x; a0.y += w0.y; a0.z += w0.z; a0.w += w0.w;
        a1.x += w1.x; a1.y += w1.y; a1.z += w1.z; a1.w += w1.w;
        a2.x += w2.x; a2.y += w2.y; a2.z += w2.z; a2.w += w2.w;
        a3.x += w3.x; a3.y += w3.y; a3.z += w3.z; a3.w += w3.w;
    }
    for (; j < c; j++) {
        const int p0 = lp[j];
        float4 w0 = ((const float4*)(g_WT + (size_t)p0 * N_POST))[n4];
        a0.x += w0.x; a0.y += w0.y; a0.z += w0.z; a0.w += w0.w;
    }
    // combine partials (keeps deterministic order per lane; close to ascending-p fp32 sum)
    float4 s;
    s.x = (a0.x + a1.x) + (a2.x + a3.x);
    s.y = (a0.y + a1.y) + (a2.y + a3.y);
    s.z = (a0.z + a1.z) + (a2.z + a3.z);
    s.w = (a0.w + a1.w) + (a2.w + a3.w);
    ((float4*)(g_cur + (size_t)t * N_POST))[n4] = s;
}

// ---------------- kernel 4: LIF scan over t --------------------------------------------
// One chain per thread (2048 chains = 32 blocks x 64 threads). Software-pipelined:
// register tiles of TT timesteps, prefetched 2 tiles ahead so the L2 load latency
// (~250-580 cyc) hides behind the 12 cyc/step dependency chain. Output rows are
// per-thread contiguous, so spikes/v are buffered 4 steps and emitted as STG.128 —
// no smem transpose, no __syncthreads, nothing serializing against the chain.
#define TT 16
#define NBUF 3
__global__ void __launch_bounds__(64) k_lif_scan(float* __restrict__ out) {
    const int n = blockIdx.x * 64 + threadIdx.x;

    float* __restrict__ out_s = out + (size_t)n * SEQ_T;
    float* __restrict__ out_v = out + (size_t)N_POST * SEQ_T + (size_t)n * SEQ_T;

    float c[NBUF][TT];

    // prime the pipeline: prefetch tiles 0 and 1
#pragma unroll
    for (int b = 0; b < NBUF - 1; b++)
#pragma unroll
        for (int k = 0; k < TT; k++)
            c[b][k] = g_cur[(size_t)(b * TT + k) * N_POST + n];

    float v = 0.f;
    const int NTILES = SEQ_T / TT;

    for (int tile = 0; tile < NTILES; tile++) {
        const int cur = tile % NBUF;
        const int nxt = (tile + NBUF - 1) % NBUF;
        const int tpre = (tile + NBUF - 1) * TT;

        // issue next-next tile's loads first (deep prefetch, independent of chain)
        if (tpre < SEQ_T) {
#pragma unroll
            for (int k = 0; k < TT; k++)
                c[nxt][k] = g_cur[(size_t)(tpre + k) * N_POST + n];
        }

        // serial LIF chain on the current (already-resident) tile
        float sbuf[TT], vbuf[TT];
#pragma unroll
        for (int k = 0; k < TT; k++) {
            v = v * DECAY + c[cur][k];
            const bool f = (v >= V_TH);
            sbuf[k] = f ? 1.f : 0.f;
            v = f ? 0.f : v;
            vbuf[k] = v;
        }

        // contiguous per-thread row writes, vectorized
        const int t0 = tile * TT;
#pragma unroll
        for (int q = 0; q < TT / 4; q++) {
            ((float4*)out_s)[t0 / 4 + q] =
                make_float4(sbuf[4 * q], sbuf[4 * q + 1], sbuf[4 * q + 2], sbuf[4 * q + 3]);
            ((float4*)out_v)[t0 / 4 + q] =
                make_float4(vbuf[4 * q], vbuf[4 * q + 1], vbuf[4 * q + 2], vbuf[4 * q + 3]);
        }
    }
}

// ---------------- launch --------------------------------------------------------------
extern "C" void kernel_launch(void* const* d_in, const int* in_sizes, int n_in,
                              void* d_out, int out_size) {
    const float* stim = (const float*)d_in[0];   // [N_PRE, SEQ_T]
    const float* W    = (const float*)d_in[1];   // [N_POST, N_PRE]
    // defensive: auto-detect input order by element counts (they differ: 4M vs 2M)
    if (n_in >= 2 && in_sizes[0] == N_POST * N_PRE && in_sizes[1] == N_PRE * SEQ_T) {
        const float* tmp = stim; stim = W; W = tmp;
    }
    float* out = (float*)d_out;

    // 1) transpose W  and 2) build active lists
    k_transpose<<<dim3(N_PRE / 32, N_POST / 32), dim3(32, 8)>>>(W);
    k_build_lists<<<SEQ_T / 256, 256>>>(stim);

    // 3) sparse gather: currents[t][n]
    k_gather<<<dim3(SEQ_T, N_POST / 1024), 256>>>();

    // 4) LIF scan, direct vectorized row output
    k_lif_scan<<<N_POST / 64, 64>>>(out);
}